// round 9
// baseline (speedup 1.0000x reference)
#include <cuda_runtime.h>
#include <cuda_fp16.h>
#include <mma.h>

using namespace nvcuda;

#define Nn 50000
#define Ee 800000
#define Hh 4

// ---------------- persistent scratch (no allocations allowed) ----------------
__device__ float   g_h[Nn * 256];    // pre-aggregation features fp32
__device__ __align__(128) __half2 g_hh[Nn * 128];  // pre-agg features fp16 (L3/L4 gather)
__device__ float   g_act[Nn * 256];  // post-aggregation activations fp32
__device__ __align__(128) __half g_ahi[Nn * 256];  // activations split-hi
__device__ __align__(128) __half g_alo[Nn * 256];  // activations split-lo
__device__ __align__(128) __half g_xhi[Nn * 128];  // input x split-hi
__device__ __align__(128) __half g_xlo[Nn * 128];  // input x split-lo
__device__ __align__(128) __half g_w1hi[4096],  g_w1lo[4096];
__device__ __align__(128) __half g_w2hi[2048],  g_w2lo[2048];
__device__ __align__(128) __half g_w3hi[8192],  g_w3lo[8192];
__device__ __align__(128) __half g_w4hi[32768], g_w4lo[32768];
__device__ float   g_as[Nn * Hh];
__device__ float   g_ad[Nn * Hh];
__device__ float   g_pv[Ee * Hh];
__device__ int     g_counts[Nn];
__device__ int     g_starts[Nn];
__device__ int     g_cursor[Nn];
__device__ int     g_csr[Ee];
__device__ int     g_edst[Ee];
__device__ int     g_bsum[64];

__device__ __forceinline__ void fsplit(float v, __half& hi, __half& lo) {
    hi = __float2half_rn(v);
    lo = __float2half_rn(v - __half2float(hi));
}

// ---------------- fp32 -> split-fp16 conversions (x and all W) ----------------
__global__ void conv_k(const float* __restrict__ x,  const float* __restrict__ W1,
                       const float* __restrict__ W2, const float* __restrict__ W3,
                       const float* __restrict__ W4) {
    const int NX = Nn * 128;
    int i = blockIdx.x * 256 + threadIdx.x;
    if (i < NX) {
        fsplit(x[i], g_xhi[i], g_xlo[i]);
        return;
    }
    int j = i - NX;
    if (j < 4096) {
        fsplit(W1[j], g_w1hi[j], g_w1lo[j]);
    } else if (j < 4096 + 2048) {
        int p = j - 4096;
        fsplit(W2[p], g_w2hi[p], g_w2lo[p]);
    } else if (j < 6144 + 8192) {
        int p = j - 6144;
        fsplit(W3[p], g_w3hi[p], g_w3lo[p]);
    } else if (j < 14336 + 32768) {
        int p = j - 14336;
        fsplit(W4[p], g_w4hi[p], g_w4lo[p]);
    }
}

// ---------------- CSR build ----------------
__global__ void zero_k() {
    int i = blockIdx.x * blockDim.x + threadIdx.x;
    if (i < Nn) { g_counts[i] = 0; g_cursor[i] = 0; }
}

__global__ void hist_k(const int* __restrict__ ei) {
    int e = blockIdx.x * blockDim.x + threadIdx.x;
    if (e < Ee) atomicAdd(&g_counts[ei[Ee + e]], 1);
}

__global__ void scan1_k() {
    __shared__ int sh[1024];
    int t = threadIdx.x;
    int i = blockIdx.x * 1024 + t;
    int v = (i < Nn) ? g_counts[i] : 0;
    sh[t] = v;
    __syncthreads();
    #pragma unroll
    for (int off = 1; off < 1024; off <<= 1) {
        int x = (t >= off) ? sh[t - off] : 0;
        __syncthreads();
        sh[t] += x;
        __syncthreads();
    }
    if (i < Nn) g_starts[i] = sh[t];
    if (t == 1023) g_bsum[blockIdx.x] = sh[1023];
}

__global__ void scan2_k() {
    __shared__ int sh[64];
    int t = threadIdx.x;
    const int NB = (Nn + 1023) / 1024;     // 49
    if (t < NB) sh[t] = g_bsum[t];
    __syncthreads();
    if (t == 0) {
        int s = 0;
        for (int i = 0; i < NB; i++) { s += sh[i]; sh[i] = s; }
    }
    __syncthreads();
    if (t < NB) g_bsum[t] = sh[t];
}

__global__ void scan3_k() {
    int i = blockIdx.x * 1024 + threadIdx.x;
    if (i >= Nn) return;
    int off = (blockIdx.x > 0) ? g_bsum[blockIdx.x - 1] : 0;
    g_starts[i] = g_starts[i] - g_counts[i] + off;
}

__global__ void fill_k(const int* __restrict__ ei) {
    int e = blockIdx.x * blockDim.x + threadIdx.x;
    if (e >= Ee) return;
    int src = ei[e];
    int dst = ei[Ee + e];
    int pos = g_starts[dst] + atomicAdd(&g_cursor[dst], 1);
    g_csr[pos]  = src;
    g_edst[pos] = dst;
}

// ---------------- split-fp16 tensor-core GEMM (fp32-accurate) ----------------
// h = (Ahi+Alo) @ (Whi+Wlo), dropping the lo*lo term. fp32 accumulate.
// Block = 4 warps; warp computes a 16 x WN strip. Writes fp32 g_h + fp16 g_hh.
template <int IN_, int OUT_, int WN>
__global__ void __launch_bounds__(128) hgemm_k(const __half* __restrict__ Ahi,
                                               const __half* __restrict__ Alo,
                                               const __half* __restrict__ Whi,
                                               const __half* __restrict__ Wlo) {
    constexpr int WPR = OUT_ / WN;       // warps per 16-row strip
    constexpr int MT  = 4 / WPR;         // m-tiles per block
    constexpr int NF  = WN / 16;         // b-fragments per warp
    __shared__ __align__(32) float sw[4 * 16 * WN];

    int w    = threadIdx.x / 32;
    int lane = threadIdx.x % 32;
    int mt   = w / WPR;
    int nc0  = (w % WPR) * WN;
    int m0   = blockIdx.x * (MT * 16) + mt * 16;
    if (m0 >= Nn) return;                // Nn % 16 == 0: tiles never straddle

    wmma::fragment<wmma::accumulator, 16, 16, 16, float> acc[NF];
    #pragma unroll
    for (int c = 0; c < NF; c++) wmma::fill_fragment(acc[c], 0.0f);

    wmma::fragment<wmma::matrix_a, 16, 16, 16, __half, wmma::row_major> afh, afl;
    wmma::fragment<wmma::matrix_b, 16, 16, 16, __half, wmma::row_major> bfh, bfl;

    #pragma unroll
    for (int k0 = 0; k0 < IN_; k0 += 16) {
        wmma::load_matrix_sync(afh, Ahi + m0 * IN_ + k0, IN_);
        wmma::load_matrix_sync(afl, Alo + m0 * IN_ + k0, IN_);
        #pragma unroll
        for (int c = 0; c < NF; c++) {
            wmma::load_matrix_sync(bfh, Whi + k0 * OUT_ + nc0 + c * 16, OUT_);
            wmma::load_matrix_sync(bfl, Wlo + k0 * OUT_ + nc0 + c * 16, OUT_);
            wmma::mma_sync(acc[c], afh, bfh, acc[c]);
            wmma::mma_sync(acc[c], afl, bfh, acc[c]);
            wmma::mma_sync(acc[c], afh, bfl, acc[c]);
        }
    }

    float* mysw = &sw[w * 16 * WN];
    #pragma unroll
    for (int c = 0; c < NF; c++)
        wmma::store_matrix_sync(mysw + c * 16, acc[c], WN, wmma::mem_row_major);
    __syncwarp();

    for (int i = lane; i < 16 * WN / 4; i += 32) {
        int r  = i / (WN / 4);
        int c4 = (i % (WN / 4)) * 4;
        float4 v = *reinterpret_cast<float4*>(&mysw[r * WN + c4]);
        int row = m0 + r;
        *reinterpret_cast<float4*>(&g_h[row * OUT_ + nc0 + c4]) = v;
        __half2 ha = __floats2half2_rn(v.x, v.y);
        __half2 hb = __floats2half2_rn(v.z, v.w);
        uint2 u;
        u.x = *reinterpret_cast<unsigned*>(&ha);
        u.y = *reinterpret_cast<unsigned*>(&hb);
        *reinterpret_cast<uint2*>(&g_hh[row * (OUT_ / 2) + (nc0 + c4) / 2]) = u;
    }
}

// ---------------- per-node attention logits ----------------
template <int C>
__global__ void alpha_k(const float* __restrict__ a_src, const float* __restrict__ a_dst) {
    int i = blockIdx.x * blockDim.x + threadIdx.x;
    if (i >= Nn * Hh) return;
    int node = i >> 2, head = i & 3;
    const float4* hp = reinterpret_cast<const float4*>(&g_h[node * (Hh * C) + head * C]);
    const float4* sp = reinterpret_cast<const float4*>(&a_src[head * C]);
    const float4* dp = reinterpret_cast<const float4*>(&a_dst[head * C]);
    float ss = 0.f, sd = 0.f;
    #pragma unroll
    for (int c = 0; c < C / 4; c++) {
        float4 v = hp[c];
        float4 s = __ldg(&sp[c]);
        float4 d = __ldg(&dp[c]);
        ss = fmaf(v.x, s.x, fmaf(v.y, s.y, fmaf(v.z, s.z, fmaf(v.w, s.w, ss))));
        sd = fmaf(v.x, d.x, fmaf(v.y, d.y, fmaf(v.z, d.z, fmaf(v.w, d.w, sd))));
    }
    g_as[i] = ss;
    g_ad[i] = sd;
}

// ---------------- per-edge softmax numerators (all 4 heads) ----------------
__global__ void epv_k() {
    int p = blockIdx.x * blockDim.x + threadIdx.x;
    if (p >= Ee) return;
    int src = g_csr[p];
    int dst = g_edst[p];
    float4 s = *reinterpret_cast<const float4*>(&g_as[src * Hh]);
    float4 d = *reinterpret_cast<const float4*>(&g_ad[dst * Hh]);
    float4 e = make_float4(s.x + d.x, s.y + d.y, s.z + d.z, s.w + d.w);
    e.x = (e.x < 0.f) ? 0.2f * e.x : e.x;
    e.y = (e.y < 0.f) ? 0.2f * e.y : e.y;
    e.z = (e.z < 0.f) ? 0.2f * e.z : e.z;
    e.w = (e.w < 0.f) ? 0.2f * e.w : e.w;
    *reinterpret_cast<float4*>(&g_pv[p * Hh]) =
        make_float4(__expf(e.x), __expf(e.y), __expf(e.z), __expf(e.w));
}

// ---------------- per-dst aggregation (atomic-free) ----------------
// HALF: gather h in fp16 (L3/L4) or fp32 (L1/L2). Output: fp32 + split fp16.
template <int C, bool HALF>
__global__ void __launch_bounds__(256) agg_k(const float* __restrict__ bias) {
    constexpr int HC  = Hh * C;
    constexpr int TPN = HC / 4;
    constexpr int NPB = 256 / TPN;
    int t    = threadIdx.x % TPN;
    int node = blockIdx.x * NPB + threadIdx.x / TPN;
    if (node >= Nn) return;
    int g4   = t * 4;
    int head = g4 / C;

    // implicit self-loop (fp32)
    float es = g_as[node * Hh + head] + g_ad[node * Hh + head];
    es = (es < 0.f) ? 0.2f * es : es;
    float pl = __expf(es);
    float denom = pl;
    float4 hv = *reinterpret_cast<const float4*>(&g_h[node * HC + g4]);
    float4 acc = make_float4(pl * hv.x, pl * hv.y, pl * hv.z, pl * hv.w);

    int start = g_starts[node];
    int cnt   = g_counts[node];
    #pragma unroll 4
    for (int j = 0; j < cnt; j++) {
        int   src = __ldg(&g_csr[start + j]);
        float pv  = __ldg(&g_pv[(start + j) * Hh + head]);
        float4 h;
        if (HALF) {
            uint2 raw = __ldg(reinterpret_cast<const uint2*>(&g_hh[src * (HC / 2) + t * 2]));
            __half2 ha = *reinterpret_cast<__half2*>(&raw.x);
            __half2 hb = *reinterpret_cast<__half2*>(&raw.y);
            float2 fa = __half22float2(ha);
            float2 fb = __half22float2(hb);
            h = make_float4(fa.x, fa.y, fb.x, fb.y);
        } else {
            h = *reinterpret_cast<const float4*>(&g_h[src * HC + g4]);
        }
        denom += pv;
        acc.x = fmaf(pv, h.x, acc.x);
        acc.y = fmaf(pv, h.y, acc.y);
        acc.z = fmaf(pv, h.z, acc.z);
        acc.w = fmaf(pv, h.w, acc.w);
    }
    float inv = 1.0f / denom;
    float4 b = *reinterpret_cast<const float4*>(&bias[g4]);
    float4 o;
    o.x = acc.x * inv + b.x;
    o.y = acc.y * inv + b.y;
    o.z = acc.z * inv + b.z;
    o.w = acc.w * inv + b.w;
    o.x = (o.x > 0.f) ? o.x : expm1f(o.x);
    o.y = (o.y > 0.f) ? o.y : expm1f(o.y);
    o.z = (o.z > 0.f) ? o.z : expm1f(o.z);
    o.w = (o.w > 0.f) ? o.w : expm1f(o.w);
    *reinterpret_cast<float4*>(&g_act[node * HC + g4]) = o;

    // split-fp16 copy for the next layer's tensor-core GEMM
    __half hx, lx, hy, ly, hz, lz, hw, lw;
    fsplit(o.x, hx, lx); fsplit(o.y, hy, ly);
    fsplit(o.z, hz, lz); fsplit(o.w, hw, lw);
    __half2 h01 = __halves2half2(hx, hy), h23 = __halves2half2(hz, hw);
    __half2 l01 = __halves2half2(lx, ly), l23 = __halves2half2(lz, lw);
    uint2 uh, ul;
    uh.x = *reinterpret_cast<unsigned*>(&h01);
    uh.y = *reinterpret_cast<unsigned*>(&h23);
    ul.x = *reinterpret_cast<unsigned*>(&l01);
    ul.y = *reinterpret_cast<unsigned*>(&l23);
    *reinterpret_cast<uint2*>(&g_ahi[node * HC + g4]) = uh;
    *reinterpret_cast<uint2*>(&g_alo[node * HC + g4]) = ul;
}

// ---------------- fused MLP head: 256 -> 32 -> 64 -> 1 ----------------
__global__ void __launch_bounds__(256) mlp_k(const float* __restrict__ Wr,  const float* __restrict__ br,
                                             const float* __restrict__ Wf1, const float* __restrict__ bf1,
                                             const float* __restrict__ Wf2, const float* __restrict__ bf2,
                                             float* __restrict__ out) {
    __shared__ float sin_[8 * 256];
    __shared__ float smid[8 * 32];
    int w = threadIdx.x / 32, lane = threadIdx.x % 32;
    int nodeBase = blockIdx.x * 8;

    for (int idx = threadIdx.x; idx < 8 * 256; idx += 256) {
        int node = nodeBase + idx / 256;
        sin_[idx] = (node < Nn) ? g_act[node * 256 + (idx % 256)] : 0.f;
    }
    __syncthreads();

    int node = nodeBase + w;
    float acc = br[lane];
    #pragma unroll 4
    for (int k = 0; k < 256; k++) acc = fmaf(sin_[w * 256 + k], Wr[k * 32 + lane], acc);
    acc = (acc > 0.f) ? acc : expm1f(acc);
    smid[w * 32 + lane] = acc;
    __syncwarp();
    float f0 = bf1[lane], f1 = bf1[lane + 32];
    #pragma unroll
    for (int k = 0; k < 32; k++) {
        float m = smid[w * 32 + k];
        f0 = fmaf(m, Wf1[k * 64 + lane],      f0);
        f1 = fmaf(m, Wf1[k * 64 + lane + 32], f1);
    }
    f0 = (f0 > 0.f) ? f0 : expm1f(f0);
    f1 = (f1 > 0.f) ? f1 : expm1f(f1);
    float part = f0 * Wf2[lane] + f1 * Wf2[lane + 32];
    #pragma unroll
    for (int off = 16; off; off >>= 1) part += __shfl_xor_sync(0xffffffff, part, off);
    if (lane == 0 && node < Nn) out[node] = part + bf2[0];
}

// ---------------- launch ----------------
extern "C" void kernel_launch(void* const* d_in, const int* in_sizes, int n_in,
                              void* d_out, int out_size) {
    const float* x   = (const float*)d_in[0];
    const int*   ei  = (const int*)  d_in[1];
    const float* W1  = (const float*)d_in[3];
    const float* as1 = (const float*)d_in[4];
    const float* ad1 = (const float*)d_in[5];
    const float* b1  = (const float*)d_in[6];
    const float* W2  = (const float*)d_in[7];
    const float* as2 = (const float*)d_in[8];
    const float* ad2 = (const float*)d_in[9];
    const float* b2  = (const float*)d_in[10];
    const float* W3  = (const float*)d_in[11];
    const float* as3 = (const float*)d_in[12];
    const float* ad3 = (const float*)d_in[13];
    const float* b3  = (const float*)d_in[14];
    const float* W4  = (const float*)d_in[15];
    const float* as4 = (const float*)d_in[16];
    const float* ad4 = (const float*)d_in[17];
    const float* b4  = (const float*)d_in[18];
    const float* Wr  = (const float*)d_in[19];
    const float* br  = (const float*)d_in[20];
    const float* Wf1 = (const float*)d_in[21];
    const float* bf1 = (const float*)d_in[22];
    const float* Wf2 = (const float*)d_in[23];
    const float* bf2 = (const float*)d_in[24];
    float* out = (float*)d_out;

    const __half *xhi, *xlo, *ahi, *alo;
    const __half *w1hi, *w1lo, *w2hi, *w2lo, *w3hi, *w3lo, *w4hi, *w4lo;
    { void* p; cudaGetSymbolAddress(&p, g_xhi);  xhi  = (const __half*)p; }
    { void* p; cudaGetSymbolAddress(&p, g_xlo);  xlo  = (const __half*)p; }
    { void* p; cudaGetSymbolAddress(&p, g_ahi);  ahi  = (const __half*)p; }
    { void* p; cudaGetSymbolAddress(&p, g_alo);  alo  = (const __half*)p; }
    { void* p; cudaGetSymbolAddress(&p, g_w1hi); w1hi = (const __half*)p; }
    { void* p; cudaGetSymbolAddress(&p, g_w1lo); w1lo = (const __half*)p; }
    { void* p; cudaGetSymbolAddress(&p, g_w2hi); w2hi = (const __half*)p; }
    { void* p; cudaGetSymbolAddress(&p, g_w2lo); w2lo = (const __half*)p; }
    { void* p; cudaGetSymbolAddress(&p, g_w3hi); w3hi = (const __half*)p; }
    { void* p; cudaGetSymbolAddress(&p, g_w3lo); w3lo = (const __half*)p; }
    { void* p; cudaGetSymbolAddress(&p, g_w4hi); w4hi = (const __half*)p; }
    { void* p; cudaGetSymbolAddress(&p, g_w4lo); w4lo = (const __half*)p; }

    const int NB_SCAN = (Nn + 1023) / 1024;
    const int EB = (Ee + 255) / 256;
    const int AB = (Nn * Hh + 255) / 256;
    const int CONV_N = Nn * 128 + 4096 + 2048 + 8192 + 32768;

    conv_k<<<(CONV_N + 255) / 256, 256>>>(x, W1, W2, W3, W4);   // 1
    zero_k<<<(Nn + 255) / 256, 256>>>();                         // 2
    hist_k<<<EB, 256>>>(ei);                                     // 3
    // 4 — profiled slot: layer-1 split tensor-core GEMM (128 -> 32)
    hgemm_k<128, 32, 32><<<(Nn + 63) / 64, 128>>>(xhi, xlo, w1hi, w1lo);
    scan1_k<<<NB_SCAN, 1024>>>();
    scan2_k<<<1, 64>>>();
    scan3_k<<<NB_SCAN, 1024>>>();
    fill_k<<<EB, 256>>>(ei);

    // Layer 1 (gemm done)
    alpha_k<8><<<AB, 256>>>(as1, ad1);
    epv_k<<<EB, 256>>>();
    agg_k<8, false><<<(Nn * 8 + 255) / 256, 256>>>(b1);

    // Layer 2: 32 -> 64
    hgemm_k<32, 64, 64><<<(Nn + 63) / 64, 128>>>(ahi, alo, w2hi, w2lo);
    alpha_k<16><<<AB, 256>>>(as2, ad2);
    epv_k<<<EB, 256>>>();
    agg_k<16, false><<<(Nn * 16 + 255) / 256, 256>>>(b2);

    // Layer 3: 64 -> 128
    hgemm_k<64, 128, 128><<<(Nn + 63) / 64, 128>>>(ahi, alo, w3hi, w3lo);
    alpha_k<32><<<AB, 256>>>(as3, ad3);
    epv_k<<<EB, 256>>>();
    agg_k<32, true><<<(Nn * 32 + 255) / 256, 256>>>(b3);

    // Layer 4: 128 -> 256 (2 warps per row-strip)
    hgemm_k<128, 256, 128><<<(Nn + 31) / 32, 128>>>(ahi, alo, w4hi, w4lo);
    alpha_k<64><<<AB, 256>>>(as4, ad4);
    epv_k<<<EB, 256>>>();
    agg_k<64, true><<<(Nn * 64 + 255) / 256, 256>>>(b4);

    // MLP head
    mlp_k<<<(Nn + 7) / 8, 256>>>(Wr, br, Wf1, bf1, Wf2, bf2, out);
}

// round 12
// speedup vs baseline: 1.2011x; 1.2011x over previous
#include <cuda_runtime.h>
#include <cuda_fp16.h>
#include <mma.h>

using namespace nvcuda;

#define Nn 50000
#define Ee 800000
#define Hh 4

// ---------------- persistent scratch (no allocations allowed) ----------------
__device__ float   g_h[Nn * 256];    // pre-aggregation features fp32
__device__ __align__(128) __half2 g_hh[Nn * 128];  // pre-agg features fp16 (L3/L4 gather)
__device__ float   g_act[Nn * 256];  // post-aggregation activations fp32
__device__ __align__(128) __half g_ahi[Nn * 256];  // activations split-hi
__device__ __align__(128) __half g_alo[Nn * 256];  // activations split-lo
__device__ __align__(128) __half g_xhi[Nn * 128];  // input x split-hi
__device__ __align__(128) __half g_xlo[Nn * 128];  // input x split-lo
__device__ __align__(128) __half g_w1hi[4096],  g_w1lo[4096];
__device__ __align__(128) __half g_w2hi[2048],  g_w2lo[2048];
__device__ __align__(128) __half g_w3hi[8192],  g_w3lo[8192];
__device__ __align__(128) __half g_w4hi[32768], g_w4lo[32768];
__device__ float   g_as[Nn * Hh];
__device__ float   g_ad[Nn * Hh];
__device__ float   g_pv[Ee * Hh];
__device__ int     g_counts[Nn];
__device__ int     g_starts[Nn];
__device__ int     g_cursor[Nn];
__device__ int     g_csr[Ee];
__device__ int     g_edst[Ee];
__device__ int     g_bsum[64];

__device__ __forceinline__ void fsplit(float v, __half& hi, __half& lo) {
    hi = __float2half_rn(v);
    lo = __float2half_rn(v - __half2float(hi));
}

// ---------------- fp32 -> split-fp16 conversions (x and all W) ----------------
__global__ void conv_k(const float* __restrict__ x,  const float* __restrict__ W1,
                       const float* __restrict__ W2, const float* __restrict__ W3,
                       const float* __restrict__ W4) {
    const int NX = Nn * 128;
    int i = blockIdx.x * 256 + threadIdx.x;
    if (i < NX) {
        fsplit(x[i], g_xhi[i], g_xlo[i]);
        return;
    }
    int j = i - NX;
    if (j < 4096) {
        fsplit(W1[j], g_w1hi[j], g_w1lo[j]);
    } else if (j < 4096 + 2048) {
        int p = j - 4096;
        fsplit(W2[p], g_w2hi[p], g_w2lo[p]);
    } else if (j < 6144 + 8192) {
        int p = j - 6144;
        fsplit(W3[p], g_w3hi[p], g_w3lo[p]);
    } else if (j < 14336 + 32768) {
        int p = j - 14336;
        fsplit(W4[p], g_w4hi[p], g_w4lo[p]);
    }
}

// ---------------- CSR build ----------------
__global__ void zero_k() {
    int i = blockIdx.x * blockDim.x + threadIdx.x;
    if (i < Nn) { g_counts[i] = 0; g_cursor[i] = 0; }
}

__global__ void hist_k(const int* __restrict__ ei) {
    int e = blockIdx.x * blockDim.x + threadIdx.x;
    if (e < Ee) atomicAdd(&g_counts[ei[Ee + e]], 1);
}

__global__ void scan1_k() {
    __shared__ int sh[1024];
    int t = threadIdx.x;
    int i = blockIdx.x * 1024 + t;
    int v = (i < Nn) ? g_counts[i] : 0;
    sh[t] = v;
    __syncthreads();
    #pragma unroll
    for (int off = 1; off < 1024; off <<= 1) {
        int x = (t >= off) ? sh[t - off] : 0;
        __syncthreads();
        sh[t] += x;
        __syncthreads();
    }
    if (i < Nn) g_starts[i] = sh[t];
    if (t == 1023) g_bsum[blockIdx.x] = sh[1023];
}

__global__ void scan2_k() {
    __shared__ int sh[64];
    int t = threadIdx.x;
    const int NB = (Nn + 1023) / 1024;     // 49
    if (t < NB) sh[t] = g_bsum[t];
    __syncthreads();
    if (t == 0) {
        int s = 0;
        for (int i = 0; i < NB; i++) { s += sh[i]; sh[i] = s; }
    }
    __syncthreads();
    if (t < NB) g_bsum[t] = sh[t];
}

__global__ void scan3_k() {
    int i = blockIdx.x * 1024 + threadIdx.x;
    if (i >= Nn) return;
    int off = (blockIdx.x > 0) ? g_bsum[blockIdx.x - 1] : 0;
    g_starts[i] = g_starts[i] - g_counts[i] + off;
}

__global__ void fill_k(const int* __restrict__ ei) {
    int e = blockIdx.x * blockDim.x + threadIdx.x;
    if (e >= Ee) return;
    int src = ei[e];
    int dst = ei[Ee + e];
    int pos = g_starts[dst] + atomicAdd(&g_cursor[dst], 1);
    g_csr[pos]  = src;
    g_edst[pos] = dst;
}

// ---------------- smem-staged split-fp16 tensor-core GEMM ----------------
// h = (Ahi+Alo) @ (Whi+Wlo), lo*lo dropped, fp32 accumulate. Writes fp32 g_h.
// Warp grid WM x WNW; each warp: MT m-tiles x NF n-fragments.
template <int IN_, int OUT_, int WM, int WNW, int MT, int NF, int KC>
__global__ void __launch_bounds__(WM * WNW * 32) hgemm_k(const __half* __restrict__ Ahi,
                                                         const __half* __restrict__ Alo,
                                                         const __half* __restrict__ Whi,
                                                         const __half* __restrict__ Wlo) {
    constexpr int NT  = WM * WNW * 32;
    constexpr int MB  = WM * MT * 16;       // block rows
    constexpr int LDA = KC + 8;             // padded (bank-rotating) strides
    constexpr int LDW = OUT_ + 8;
    static_assert(WNW * NF * 16 == OUT_, "col tiling must cover OUT");

    __shared__ __align__(16) __half sAh[MB * LDA];
    __shared__ __align__(16) __half sAl[MB * LDA];
    __shared__ __align__(16) __half sWh[KC * LDW];
    __shared__ __align__(16) __half sWl[KC * LDW];

    int w   = threadIdx.x / 32;
    int wm  = w / WNW;
    int wn  = w % WNW;
    int m0  = blockIdx.x * MB + wm * MT * 16;
    int nc0 = wn * NF * 16;

    wmma::fragment<wmma::accumulator, 16, 16, 16, float> acc[MT][NF];
    #pragma unroll
    for (int mi = 0; mi < MT; mi++)
        #pragma unroll
        for (int ni = 0; ni < NF; ni++) wmma::fill_fragment(acc[mi][ni], 0.0f);

    for (int kc0 = 0; kc0 < IN_; kc0 += KC) {
        // stage A chunk (hi+lo), zero-pad OOB rows
        for (int idx = threadIdx.x; idx < MB * (KC / 4); idx += NT) {
            int r  = idx / (KC / 4);
            int c4 = (idx % (KC / 4)) * 4;
            int row = blockIdx.x * MB + r;
            uint2 vh = make_uint2(0u, 0u), vl = make_uint2(0u, 0u);
            if (row < Nn) {
                vh = *reinterpret_cast<const uint2*>(&Ahi[row * IN_ + kc0 + c4]);
                vl = *reinterpret_cast<const uint2*>(&Alo[row * IN_ + kc0 + c4]);
            }
            *reinterpret_cast<uint2*>(&sAh[r * LDA + c4]) = vh;
            *reinterpret_cast<uint2*>(&sAl[r * LDA + c4]) = vl;
        }
        // stage W chunk (hi+lo)
        for (int idx = threadIdx.x; idx < KC * (OUT_ / 4); idx += NT) {
            int r  = idx / (OUT_ / 4);
            int c4 = (idx % (OUT_ / 4)) * 4;
            *reinterpret_cast<uint2*>(&sWh[r * LDW + c4]) =
                *reinterpret_cast<const uint2*>(&Whi[(kc0 + r) * OUT_ + c4]);
            *reinterpret_cast<uint2*>(&sWl[r * LDW + c4]) =
                *reinterpret_cast<const uint2*>(&Wlo[(kc0 + r) * OUT_ + c4]);
        }
        __syncthreads();

        #pragma unroll
        for (int kt = 0; kt < KC / 16; kt++) {
            wmma::fragment<wmma::matrix_a, 16, 16, 16, __half, wmma::row_major> afh[MT], afl[MT];
            #pragma unroll
            for (int mi = 0; mi < MT; mi++) {
                const __half* ap = &sAh[(wm * MT * 16 + mi * 16) * LDA + kt * 16];
                const __half* lp = &sAl[(wm * MT * 16 + mi * 16) * LDA + kt * 16];
                wmma::load_matrix_sync(afh[mi], ap, LDA);
                wmma::load_matrix_sync(afl[mi], lp, LDA);
            }
            #pragma unroll
            for (int ni = 0; ni < NF; ni++) {
                wmma::fragment<wmma::matrix_b, 16, 16, 16, __half, wmma::row_major> bfh, bfl;
                wmma::load_matrix_sync(bfh, &sWh[kt * 16 * LDW + nc0 + ni * 16], LDW);
                wmma::load_matrix_sync(bfl, &sWl[kt * 16 * LDW + nc0 + ni * 16], LDW);
                #pragma unroll
                for (int mi = 0; mi < MT; mi++) {
                    wmma::mma_sync(acc[mi][ni], afh[mi], bfh, acc[mi][ni]);
                    wmma::mma_sync(acc[mi][ni], afl[mi], bfh, acc[mi][ni]);
                    wmma::mma_sync(acc[mi][ni], afh[mi], bfl, acc[mi][ni]);
                }
            }
        }
        __syncthreads();
    }

    // epilogue: store fp32 straight to global (tiles never straddle Nn: 50000 % 16 == 0)
    #pragma unroll
    for (int mi = 0; mi < MT; mi++) {
        int row = m0 + mi * 16;
        if (row >= Nn) break;
        #pragma unroll
        for (int ni = 0; ni < NF; ni++)
            wmma::store_matrix_sync(&g_h[row * OUT_ + nc0 + ni * 16], acc[mi][ni],
                                    OUT_, wmma::mem_row_major);
    }
}

// ---------------- per-node attention logits (+ fp16 copy for L3/L4 gather) ----------------
template <int C, bool WH>
__global__ void alpha_k(const float* __restrict__ a_src, const float* __restrict__ a_dst) {
    int i = blockIdx.x * blockDim.x + threadIdx.x;
    if (i >= Nn * Hh) return;
    int node = i >> 2, head = i & 3;
    constexpr int HC = Hh * C;
    const float4* hp = reinterpret_cast<const float4*>(&g_h[node * HC + head * C]);
    const float4* sp = reinterpret_cast<const float4*>(&a_src[head * C]);
    const float4* dp = reinterpret_cast<const float4*>(&a_dst[head * C]);
    float ss = 0.f, sd = 0.f;
    #pragma unroll
    for (int c = 0; c < C / 4; c++) {
        float4 v = hp[c];
        float4 s = __ldg(&sp[c]);
        float4 d = __ldg(&dp[c]);
        ss = fmaf(v.x, s.x, fmaf(v.y, s.y, fmaf(v.z, s.z, fmaf(v.w, s.w, ss))));
        sd = fmaf(v.x, d.x, fmaf(v.y, d.y, fmaf(v.z, d.z, fmaf(v.w, d.w, sd))));
        if (WH) {
            __half2 ha = __floats2half2_rn(v.x, v.y);
            __half2 hb = __floats2half2_rn(v.z, v.w);
            uint2 u;
            u.x = *reinterpret_cast<unsigned*>(&ha);
            u.y = *reinterpret_cast<unsigned*>(&hb);
            *reinterpret_cast<uint2*>(&g_hh[node * (HC / 2) + head * (C / 2) + c * 2]) = u;
        }
    }
    g_as[i] = ss;
    g_ad[i] = sd;
}

// ---------------- per-edge softmax numerators (all 4 heads) ----------------
__global__ void epv_k() {
    int p = blockIdx.x * blockDim.x + threadIdx.x;
    if (p >= Ee) return;
    int src = g_csr[p];
    int dst = g_edst[p];
    float4 s = *reinterpret_cast<const float4*>(&g_as[src * Hh]);
    float4 d = *reinterpret_cast<const float4*>(&g_ad[dst * Hh]);
    float4 e = make_float4(s.x + d.x, s.y + d.y, s.z + d.z, s.w + d.w);
    e.x = (e.x < 0.f) ? 0.2f * e.x : e.x;
    e.y = (e.y < 0.f) ? 0.2f * e.y : e.y;
    e.z = (e.z < 0.f) ? 0.2f * e.z : e.z;
    e.w = (e.w < 0.f) ? 0.2f * e.w : e.w;
    *reinterpret_cast<float4*>(&g_pv[p * Hh]) =
        make_float4(__expf(e.x), __expf(e.y), __expf(e.z), __expf(e.w));
}

// ---------------- per-dst aggregation (atomic-free) ----------------
template <int C, bool HALF>
__global__ void __launch_bounds__(256) agg_k(const float* __restrict__ bias) {
    constexpr int HC  = Hh * C;
    constexpr int TPN = HC / 4;
    constexpr int NPB = 256 / TPN;
    int t    = threadIdx.x % TPN;
    int node = blockIdx.x * NPB + threadIdx.x / TPN;
    if (node >= Nn) return;
    int g4   = t * 4;
    int head = g4 / C;

    // implicit self-loop (fp32)
    float es = g_as[node * Hh + head] + g_ad[node * Hh + head];
    es = (es < 0.f) ? 0.2f * es : es;
    float pl = __expf(es);
    float denom = pl;
    float4 hv = *reinterpret_cast<const float4*>(&g_h[node * HC + g4]);
    float4 acc = make_float4(pl * hv.x, pl * hv.y, pl * hv.z, pl * hv.w);

    int start = g_starts[node];
    int cnt   = g_counts[node];
    #pragma unroll 4
    for (int j = 0; j < cnt; j++) {
        int   src = __ldg(&g_csr[start + j]);
        float pv  = __ldg(&g_pv[(start + j) * Hh + head]);
        float4 h;
        if (HALF) {
            uint2 raw = __ldg(reinterpret_cast<const uint2*>(&g_hh[src * (HC / 2) + t * 2]));
            __half2 ha = *reinterpret_cast<__half2*>(&raw.x);
            __half2 hb = *reinterpret_cast<__half2*>(&raw.y);
            float2 fa = __half22float2(ha);
            float2 fb = __half22float2(hb);
            h = make_float4(fa.x, fa.y, fb.x, fb.y);
        } else {
            h = *reinterpret_cast<const float4*>(&g_h[src * HC + g4]);
        }
        denom += pv;
        acc.x = fmaf(pv, h.x, acc.x);
        acc.y = fmaf(pv, h.y, acc.y);
        acc.z = fmaf(pv, h.z, acc.z);
        acc.w = fmaf(pv, h.w, acc.w);
    }
    float inv = 1.0f / denom;
    float4 b = *reinterpret_cast<const float4*>(&bias[g4]);
    float4 o;
    o.x = acc.x * inv + b.x;
    o.y = acc.y * inv + b.y;
    o.z = acc.z * inv + b.z;
    o.w = acc.w * inv + b.w;
    o.x = (o.x > 0.f) ? o.x : expm1f(o.x);
    o.y = (o.y > 0.f) ? o.y : expm1f(o.y);
    o.z = (o.z > 0.f) ? o.z : expm1f(o.z);
    o.w = (o.w > 0.f) ? o.w : expm1f(o.w);
    *reinterpret_cast<float4*>(&g_act[node * HC + g4]) = o;

    // split-fp16 copy for the next layer's tensor-core GEMM
    __half hx, lx, hy, ly, hz, lz, hw, lw;
    fsplit(o.x, hx, lx); fsplit(o.y, hy, ly);
    fsplit(o.z, hz, lz); fsplit(o.w, hw, lw);
    __half2 h01 = __halves2half2(hx, hy), h23 = __halves2half2(hz, hw);
    __half2 l01 = __halves2half2(lx, ly), l23 = __halves2half2(lz, lw);
    uint2 uh, ul;
    uh.x = *reinterpret_cast<unsigned*>(&h01);
    uh.y = *reinterpret_cast<unsigned*>(&h23);
    ul.x = *reinterpret_cast<unsigned*>(&l01);
    ul.y = *reinterpret_cast<unsigned*>(&l23);
    *reinterpret_cast<uint2*>(&g_ahi[node * HC + g4]) = uh;
    *reinterpret_cast<uint2*>(&g_alo[node * HC + g4]) = ul;
}

// ---------------- fused MLP head: 256 -> 32 -> 64 -> 1 ----------------
__global__ void __launch_bounds__(256) mlp_k(const float* __restrict__ Wr,  const float* __restrict__ br,
                                             const float* __restrict__ Wf1, const float* __restrict__ bf1,
                                             const float* __restrict__ Wf2, const float* __restrict__ bf2,
                                             float* __restrict__ out) {
    __shared__ float sin_[8 * 256];
    __shared__ float smid[8 * 32];
    int w = threadIdx.x / 32, lane = threadIdx.x % 32;
    int nodeBase = blockIdx.x * 8;

    for (int idx = threadIdx.x; idx < 8 * 256; idx += 256) {
        int node = nodeBase + idx / 256;
        sin_[idx] = (node < Nn) ? g_act[node * 256 + (idx % 256)] : 0.f;
    }
    __syncthreads();

    int node = nodeBase + w;
    float acc = br[lane];
    #pragma unroll 4
    for (int k = 0; k < 256; k++) acc = fmaf(sin_[w * 256 + k], Wr[k * 32 + lane], acc);
    acc = (acc > 0.f) ? acc : expm1f(acc);
    smid[w * 32 + lane] = acc;
    __syncwarp();
    float f0 = bf1[lane], f1 = bf1[lane + 32];
    #pragma unroll
    for (int k = 0; k < 32; k++) {
        float m = smid[w * 32 + k];
        f0 = fmaf(m, Wf1[k * 64 + lane],      f0);
        f1 = fmaf(m, Wf1[k * 64 + lane + 32], f1);
    }
    f0 = (f0 > 0.f) ? f0 : expm1f(f0);
    f1 = (f1 > 0.f) ? f1 : expm1f(f1);
    float part = f0 * Wf2[lane] + f1 * Wf2[lane + 32];
    #pragma unroll
    for (int off = 16; off; off >>= 1) part += __shfl_xor_sync(0xffffffff, part, off);
    if (lane == 0 && node < Nn) out[node] = part + bf2[0];
}

// ---------------- launch ----------------
extern "C" void kernel_launch(void* const* d_in, const int* in_sizes, int n_in,
                              void* d_out, int out_size) {
    const float* x   = (const float*)d_in[0];
    const int*   ei  = (const int*)  d_in[1];
    const float* W1  = (const float*)d_in[3];
    const float* as1 = (const float*)d_in[4];
    const float* ad1 = (const float*)d_in[5];
    const float* b1  = (const float*)d_in[6];
    const float* W2  = (const float*)d_in[7];
    const float* as2 = (const float*)d_in[8];
    const float* ad2 = (const float*)d_in[9];
    const float* b2  = (const float*)d_in[10];
    const float* W3  = (const float*)d_in[11];
    const float* as3 = (const float*)d_in[12];
    const float* ad3 = (const float*)d_in[13];
    const float* b3  = (const float*)d_in[14];
    const float* W4  = (const float*)d_in[15];
    const float* as4 = (const float*)d_in[16];
    const float* ad4 = (const float*)d_in[17];
    const float* b4  = (const float*)d_in[18];
    const float* Wr  = (const float*)d_in[19];
    const float* br  = (const float*)d_in[20];
    const float* Wf1 = (const float*)d_in[21];
    const float* bf1 = (const float*)d_in[22];
    const float* Wf2 = (const float*)d_in[23];
    const float* bf2 = (const float*)d_in[24];
    float* out = (float*)d_out;

    const __half *xhi, *xlo, *ahi, *alo;
    const __half *w1hi, *w1lo, *w2hi, *w2lo, *w3hi, *w3lo, *w4hi, *w4lo;
    { void* p; cudaGetSymbolAddress(&p, g_xhi);  xhi  = (const __half*)p; }
    { void* p; cudaGetSymbolAddress(&p, g_xlo);  xlo  = (const __half*)p; }
    { void* p; cudaGetSymbolAddress(&p, g_ahi);  ahi  = (const __half*)p; }
    { void* p; cudaGetSymbolAddress(&p, g_alo);  alo  = (const __half*)p; }
    { void* p; cudaGetSymbolAddress(&p, g_w1hi); w1hi = (const __half*)p; }
    { void* p; cudaGetSymbolAddress(&p, g_w1lo); w1lo = (const __half*)p; }
    { void* p; cudaGetSymbolAddress(&p, g_w2hi); w2hi = (const __half*)p; }
    { void* p; cudaGetSymbolAddress(&p, g_w2lo); w2lo = (const __half*)p; }
    { void* p; cudaGetSymbolAddress(&p, g_w3hi); w3hi = (const __half*)p; }
    { void* p; cudaGetSymbolAddress(&p, g_w3lo); w3lo = (const __half*)p; }
    { void* p; cudaGetSymbolAddress(&p, g_w4hi); w4hi = (const __half*)p; }
    { void* p; cudaGetSymbolAddress(&p, g_w4lo); w4lo = (const __half*)p; }

    const int NB_SCAN = (Nn + 1023) / 1024;
    const int EB = (Ee + 255) / 256;
    const int AB = (Nn * Hh + 255) / 256;
    const int CONV_N = Nn * 128 + 4096 + 2048 + 8192 + 32768;

    conv_k<<<(CONV_N + 255) / 256, 256>>>(x, W1, W2, W3, W4);   // 1
    zero_k<<<(Nn + 255) / 256, 256>>>();                         // 2
    hist_k<<<EB, 256>>>(ei);                                     // 3
    // 4 — profiled slot: L1 smem-staged split GEMM (128 -> 32). WM=4,WNW=1,MT=2,NF=2
    hgemm_k<128, 32, 4, 1, 2, 2, 32><<<(Nn + 127) / 128, 128>>>(xhi, xlo, w1hi, w1lo);
    scan1_k<<<NB_SCAN, 1024>>>();
    scan2_k<<<1, 64>>>();
    scan3_k<<<NB_SCAN, 1024>>>();
    fill_k<<<EB, 256>>>(ei);

    // Layer 1 (gemm done)
    alpha_k<8, false><<<AB, 256>>>(as1, ad1);
    epv_k<<<EB, 256>>>();
    agg_k<8, false><<<(Nn * 8 + 255) / 256, 256>>>(b1);

    // Layer 2: 32 -> 64. WM=2,WNW=2,MT=2,NF=2 (128 thr, single K chunk)
    hgemm_k<32, 64, 2, 2, 2, 2, 32><<<(Nn + 63) / 64, 128>>>(ahi, alo, w2hi, w2lo);
    alpha_k<16, false><<<AB, 256>>>(as2, ad2);
    epv_k<<<EB, 256>>>();
    agg_k<16, false><<<(Nn * 16 + 255) / 256, 256>>>(b2);

    // Layer 3: 64 -> 128. WM=2,WNW=4,MT=2,NF=2 (256 thr)
    hgemm_k<64, 128, 2, 4, 2, 2, 32><<<(Nn + 63) / 64, 256>>>(ahi, alo, w3hi, w3lo);
    alpha_k<32, true><<<AB, 256>>>(as3, ad3);
    epv_k<<<EB, 256>>>();
    agg_k<32, true><<<(Nn * 32 + 255) / 256, 256>>>(b3);

    // Layer 4: 128 -> 256. WM=2,WNW=4,MT=2,NF=4 (256 thr)
    hgemm_k<128, 256, 2, 4, 2, 4, 32><<<(Nn + 63) / 64, 256>>>(ahi, alo, w4hi, w4lo);
    alpha_k<64, true><<<AB, 256>>>(as4, ad4);
    epv_k<<<EB, 256>>>();
    agg_k<64, true><<<(Nn * 64 + 255) / 256, 256>>>(b4);

    // MLP head
    mlp_k<<<(Nn + 7) / 8, 256>>>(Wr, br, Wf1, bf1, Wf2, bf2, out);
}

// round 13
// speedup vs baseline: 1.2094x; 1.0069x over previous
#include <cuda_runtime.h>
#include <cuda_fp16.h>
#include <mma.h>

using namespace nvcuda;

#define Nn 50000
#define Ee 800000
#define Hh 4

// ---------------- persistent scratch (no allocations allowed) ----------------
__device__ float   g_h[Nn * 256];    // pre-aggregation features fp32
__device__ __align__(128) __half2 g_hh[Nn * 128];  // pre-agg features fp16 (gather)
__device__ float   g_act[Nn * 256];  // post-aggregation activations fp32
__device__ __align__(128) __half g_ahi[Nn * 256];  // activations split-hi
__device__ __align__(128) __half g_alo[Nn * 256];  // activations split-lo
__device__ __align__(128) __half g_xhi[Nn * 128];  // input x split-hi
__device__ __align__(128) __half g_xlo[Nn * 128];  // input x split-lo
__device__ __align__(128) __half g_w1hi[4096],  g_w1lo[4096];
__device__ __align__(128) __half g_w2hi[2048],  g_w2lo[2048];
__device__ __align__(128) __half g_w3hi[8192],  g_w3lo[8192];
__device__ __align__(128) __half g_w4hi[32768], g_w4lo[32768];
__device__ float   g_as[Nn * Hh];
__device__ float   g_ad[Nn * Hh];
__device__ float   g_pv[Ee * Hh];
__device__ int     g_counts[Nn];
__device__ int     g_starts[Nn];
__device__ int     g_cursor[Nn];
__device__ int     g_csr[Ee];
__device__ int     g_edst[Ee];
__device__ int     g_bsum[64];

__device__ __forceinline__ void fsplit(float v, __half& hi, __half& lo) {
    hi = __float2half_rn(v);
    lo = __float2half_rn(v - __half2float(hi));
}

// ---------------- fp32 -> split-fp16 conversions + CSR zeroing ----------------
__global__ void conv_k(const float* __restrict__ x,  const float* __restrict__ W1,
                       const float* __restrict__ W2, const float* __restrict__ W3,
                       const float* __restrict__ W4) {
    const int NX = Nn * 128;
    const int NW = 4096 + 2048 + 8192 + 32768;   // 47104
    int i = blockIdx.x * 256 + threadIdx.x;
    if (i < NX) {
        fsplit(x[i], g_xhi[i], g_xlo[i]);
        return;
    }
    int j = i - NX;
    if (j < 4096) {
        fsplit(W1[j], g_w1hi[j], g_w1lo[j]);
        return;
    } else if (j < 4096 + 2048) {
        int p = j - 4096;
        fsplit(W2[p], g_w2hi[p], g_w2lo[p]);
        return;
    } else if (j < 6144 + 8192) {
        int p = j - 6144;
        fsplit(W3[p], g_w3hi[p], g_w3lo[p]);
        return;
    } else if (j < 14336 + 32768) {
        int p = j - 14336;
        fsplit(W4[p], g_w4hi[p], g_w4lo[p]);
        return;
    }
    int k = j - NW;
    if (k < Nn) { g_counts[k] = 0; g_cursor[k] = 0; }
}

// ---------------- CSR build ----------------
__global__ void hist_k(const int* __restrict__ ei) {
    int e = blockIdx.x * blockDim.x + threadIdx.x;
    if (e < Ee) atomicAdd(&g_counts[ei[Ee + e]], 1);
}

__global__ void scan1_k() {
    __shared__ int sh[1024];
    int t = threadIdx.x;
    int i = blockIdx.x * 1024 + t;
    int v = (i < Nn) ? g_counts[i] : 0;
    sh[t] = v;
    __syncthreads();
    #pragma unroll
    for (int off = 1; off < 1024; off <<= 1) {
        int x = (t >= off) ? sh[t - off] : 0;
        __syncthreads();
        sh[t] += x;
        __syncthreads();
    }
    if (i < Nn) g_starts[i] = sh[t];
    if (t == 1023) g_bsum[blockIdx.x] = sh[1023];
}

__global__ void scan2_k() {
    __shared__ int sh[64];
    int t = threadIdx.x;
    const int NB = (Nn + 1023) / 1024;     // 49
    if (t < NB) sh[t] = g_bsum[t];
    __syncthreads();
    if (t == 0) {
        int s = 0;
        for (int i = 0; i < NB; i++) { s += sh[i]; sh[i] = s; }
    }
    __syncthreads();
    if (t < NB) g_bsum[t] = sh[t];
}

__global__ void scan3_k() {
    int i = blockIdx.x * 1024 + threadIdx.x;
    if (i >= Nn) return;
    int off = (blockIdx.x > 0) ? g_bsum[blockIdx.x - 1] : 0;
    g_starts[i] = g_starts[i] - g_counts[i] + off;
}

__global__ void fill_k(const int* __restrict__ ei) {
    int e = blockIdx.x * blockDim.x + threadIdx.x;
    if (e >= Ee) return;
    int src = ei[e];
    int dst = ei[Ee + e];
    int pos = g_starts[dst] + atomicAdd(&g_cursor[dst], 1);
    g_csr[pos]  = src;
    g_edst[pos] = dst;
}

// ---------------- smem-staged split-fp16 tensor-core GEMM ----------------
// h = (Ahi+Alo) @ (Whi+Wlo), lo*lo dropped, fp32 accumulate. Writes fp32 g_h.
template <int IN_, int OUT_, int WM, int WNW, int MT, int NF, int KC>
__global__ void __launch_bounds__(WM * WNW * 32) hgemm_k(const __half* __restrict__ Ahi,
                                                         const __half* __restrict__ Alo,
                                                         const __half* __restrict__ Whi,
                                                         const __half* __restrict__ Wlo) {
    constexpr int NT  = WM * WNW * 32;
    constexpr int MB  = WM * MT * 16;       // block rows
    constexpr int LDA = KC + 8;             // padded (bank-rotating) strides
    constexpr int LDW = OUT_ + 8;
    static_assert(WNW * NF * 16 == OUT_, "col tiling must cover OUT");

    __shared__ __align__(16) __half sAh[MB * LDA];
    __shared__ __align__(16) __half sAl[MB * LDA];
    __shared__ __align__(16) __half sWh[KC * LDW];
    __shared__ __align__(16) __half sWl[KC * LDW];

    int w   = threadIdx.x / 32;
    int wm  = w / WNW;
    int wn  = w % WNW;
    int m0  = blockIdx.x * MB + wm * MT * 16;
    int nc0 = wn * NF * 16;

    wmma::fragment<wmma::accumulator, 16, 16, 16, float> acc[MT][NF];
    #pragma unroll
    for (int mi = 0; mi < MT; mi++)
        #pragma unroll
        for (int ni = 0; ni < NF; ni++) wmma::fill_fragment(acc[mi][ni], 0.0f);

    for (int kc0 = 0; kc0 < IN_; kc0 += KC) {
        for (int idx = threadIdx.x; idx < MB * (KC / 4); idx += NT) {
            int r  = idx / (KC / 4);
            int c4 = (idx % (KC / 4)) * 4;
            int row = blockIdx.x * MB + r;
            uint2 vh = make_uint2(0u, 0u), vl = make_uint2(0u, 0u);
            if (row < Nn) {
                vh = *reinterpret_cast<const uint2*>(&Ahi[row * IN_ + kc0 + c4]);
                vl = *reinterpret_cast<const uint2*>(&Alo[row * IN_ + kc0 + c4]);
            }
            *reinterpret_cast<uint2*>(&sAh[r * LDA + c4]) = vh;
            *reinterpret_cast<uint2*>(&sAl[r * LDA + c4]) = vl;
        }
        for (int idx = threadIdx.x; idx < KC * (OUT_ / 4); idx += NT) {
            int r  = idx / (OUT_ / 4);
            int c4 = (idx % (OUT_ / 4)) * 4;
            *reinterpret_cast<uint2*>(&sWh[r * LDW + c4]) =
                *reinterpret_cast<const uint2*>(&Whi[(kc0 + r) * OUT_ + c4]);
            *reinterpret_cast<uint2*>(&sWl[r * LDW + c4]) =
                *reinterpret_cast<const uint2*>(&Wlo[(kc0 + r) * OUT_ + c4]);
        }
        __syncthreads();

        #pragma unroll
        for (int kt = 0; kt < KC / 16; kt++) {
            wmma::fragment<wmma::matrix_a, 16, 16, 16, __half, wmma::row_major> afh[MT], afl[MT];
            #pragma unroll
            for (int mi = 0; mi < MT; mi++) {
                const __half* ap = &sAh[(wm * MT * 16 + mi * 16) * LDA + kt * 16];
                const __half* lp = &sAl[(wm * MT * 16 + mi * 16) * LDA + kt * 16];
                wmma::load_matrix_sync(afh[mi], ap, LDA);
                wmma::load_matrix_sync(afl[mi], lp, LDA);
            }
            #pragma unroll
            for (int ni = 0; ni < NF; ni++) {
                wmma::fragment<wmma::matrix_b, 16, 16, 16, __half, wmma::row_major> bfh, bfl;
                wmma::load_matrix_sync(bfh, &sWh[kt * 16 * LDW + nc0 + ni * 16], LDW);
                wmma::load_matrix_sync(bfl, &sWl[kt * 16 * LDW + nc0 + ni * 16], LDW);
                #pragma unroll
                for (int mi = 0; mi < MT; mi++) {
                    wmma::mma_sync(acc[mi][ni], afh[mi], bfh, acc[mi][ni]);
                    wmma::mma_sync(acc[mi][ni], afl[mi], bfh, acc[mi][ni]);
                    wmma::mma_sync(acc[mi][ni], afh[mi], bfl, acc[mi][ni]);
                }
            }
        }
        __syncthreads();
    }

    #pragma unroll
    for (int mi = 0; mi < MT; mi++) {
        int row = m0 + mi * 16;
        if (row >= Nn) break;
        #pragma unroll
        for (int ni = 0; ni < NF; ni++)
            wmma::store_matrix_sync(&g_h[row * OUT_ + nc0 + ni * 16], acc[mi][ni],
                                    OUT_, wmma::mem_row_major);
    }
}

// ---------------- per-node attention logits (+ fp16 copy for agg gather) ----------------
template <int C>
__global__ void alpha_k(const float* __restrict__ a_src, const float* __restrict__ a_dst) {
    int i = blockIdx.x * blockDim.x + threadIdx.x;
    if (i >= Nn * Hh) return;
    int node = i >> 2, head = i & 3;
    constexpr int HC = Hh * C;
    const float4* hp = reinterpret_cast<const float4*>(&g_h[node * HC + head * C]);
    const float4* sp = reinterpret_cast<const float4*>(&a_src[head * C]);
    const float4* dp = reinterpret_cast<const float4*>(&a_dst[head * C]);
    float ss = 0.f, sd = 0.f;
    #pragma unroll
    for (int c = 0; c < C / 4; c++) {
        float4 v = hp[c];
        float4 s = __ldg(&sp[c]);
        float4 d = __ldg(&dp[c]);
        ss = fmaf(v.x, s.x, fmaf(v.y, s.y, fmaf(v.z, s.z, fmaf(v.w, s.w, ss))));
        sd = fmaf(v.x, d.x, fmaf(v.y, d.y, fmaf(v.z, d.z, fmaf(v.w, d.w, sd))));
        __half2 ha = __floats2half2_rn(v.x, v.y);
        __half2 hb = __floats2half2_rn(v.z, v.w);
        uint2 u;
        u.x = *reinterpret_cast<unsigned*>(&ha);
        u.y = *reinterpret_cast<unsigned*>(&hb);
        *reinterpret_cast<uint2*>(&g_hh[node * (HC / 2) + head * (C / 2) + c * 2]) = u;
    }
    g_as[i] = ss;
    g_ad[i] = sd;
}

// ---------------- per-edge softmax numerators (all 4 heads) ----------------
__global__ void epv_k() {
    int p = blockIdx.x * blockDim.x + threadIdx.x;
    if (p >= Ee) return;
    int src = g_csr[p];
    int dst = g_edst[p];
    float4 s = *reinterpret_cast<const float4*>(&g_as[src * Hh]);
    float4 d = *reinterpret_cast<const float4*>(&g_ad[dst * Hh]);
    float4 e = make_float4(s.x + d.x, s.y + d.y, s.z + d.z, s.w + d.w);
    e.x = (e.x < 0.f) ? 0.2f * e.x : e.x;
    e.y = (e.y < 0.f) ? 0.2f * e.y : e.y;
    e.z = (e.z < 0.f) ? 0.2f * e.z : e.z;
    e.w = (e.w < 0.f) ? 0.2f * e.w : e.w;
    *reinterpret_cast<float4*>(&g_pv[p * Hh]) =
        make_float4(__expf(e.x), __expf(e.y), __expf(e.z), __expf(e.w));
}

// ---------------- per-dst aggregation (atomic-free, fp16 gather all layers) ----------------
template <int C>
__global__ void __launch_bounds__(256) agg_k(const float* __restrict__ bias) {
    constexpr int HC  = Hh * C;
    constexpr int TPN = HC / 4;
    constexpr int NPB = 256 / TPN;
    int t    = threadIdx.x % TPN;
    int node = blockIdx.x * NPB + threadIdx.x / TPN;
    if (node >= Nn) return;
    int g4   = t * 4;
    int head = g4 / C;

    // implicit self-loop (fp32)
    float es = g_as[node * Hh + head] + g_ad[node * Hh + head];
    es = (es < 0.f) ? 0.2f * es : es;
    float pl = __expf(es);
    float denom = pl;
    float4 hv = *reinterpret_cast<const float4*>(&g_h[node * HC + g4]);
    float4 acc = make_float4(pl * hv.x, pl * hv.y, pl * hv.z, pl * hv.w);

    int start = g_starts[node];
    int cnt   = g_counts[node];
    #pragma unroll 4
    for (int j = 0; j < cnt; j++) {
        int   src = __ldg(&g_csr[start + j]);
        float pv  = __ldg(&g_pv[(start + j) * Hh + head]);
        uint2 raw = __ldg(reinterpret_cast<const uint2*>(&g_hh[src * (HC / 2) + t * 2]));
        __half2 ha = *reinterpret_cast<__half2*>(&raw.x);
        __half2 hb = *reinterpret_cast<__half2*>(&raw.y);
        float2 fa = __half22float2(ha);
        float2 fb = __half22float2(hb);
        denom += pv;
        acc.x = fmaf(pv, fa.x, acc.x);
        acc.y = fmaf(pv, fa.y, acc.y);
        acc.z = fmaf(pv, fb.x, acc.z);
        acc.w = fmaf(pv, fb.y, acc.w);
    }
    float inv = 1.0f / denom;
    float4 b = *reinterpret_cast<const float4*>(&bias[g4]);
    float4 o;
    o.x = acc.x * inv + b.x;
    o.y = acc.y * inv + b.y;
    o.z = acc.z * inv + b.z;
    o.w = acc.w * inv + b.w;
    o.x = (o.x > 0.f) ? o.x : expm1f(o.x);
    o.y = (o.y > 0.f) ? o.y : expm1f(o.y);
    o.z = (o.z > 0.f) ? o.z : expm1f(o.z);
    o.w = (o.w > 0.f) ? o.w : expm1f(o.w);
    *reinterpret_cast<float4*>(&g_act[node * HC + g4]) = o;

    // split-fp16 copy for the next layer's tensor-core GEMM
    __half hx, lx, hy, ly, hz, lz, hw, lw;
    fsplit(o.x, hx, lx); fsplit(o.y, hy, ly);
    fsplit(o.z, hz, lz); fsplit(o.w, hw, lw);
    __half2 h01 = __halves2half2(hx, hy), h23 = __halves2half2(hz, hw);
    __half2 l01 = __halves2half2(lx, ly), l23 = __halves2half2(lz, lw);
    uint2 uh, ul;
    uh.x = *reinterpret_cast<unsigned*>(&h01);
    uh.y = *reinterpret_cast<unsigned*>(&h23);
    ul.x = *reinterpret_cast<unsigned*>(&l01);
    ul.y = *reinterpret_cast<unsigned*>(&l23);
    *reinterpret_cast<uint2*>(&g_ahi[node * HC + g4]) = uh;
    *reinterpret_cast<uint2*>(&g_alo[node * HC + g4]) = ul;
}

// ---------------- fused MLP head: 256 -> 32 -> 64 -> 1 ----------------
__global__ void __launch_bounds__(256) mlp_k(const float* __restrict__ Wr,  const float* __restrict__ br,
                                             const float* __restrict__ Wf1, const float* __restrict__ bf1,
                                             const float* __restrict__ Wf2, const float* __restrict__ bf2,
                                             float* __restrict__ out) {
    __shared__ float sin_[8 * 256];
    __shared__ float smid[8 * 32];
    int w = threadIdx.x / 32, lane = threadIdx.x % 32;
    int nodeBase = blockIdx.x * 8;

    for (int idx = threadIdx.x; idx < 8 * 256; idx += 256) {
        int node = nodeBase + idx / 256;
        sin_[idx] = (node < Nn) ? g_act[node * 256 + (idx % 256)] : 0.f;
    }
    __syncthreads();

    int node = nodeBase + w;
    float acc = br[lane];
    #pragma unroll 4
    for (int k = 0; k < 256; k++) acc = fmaf(sin_[w * 256 + k], Wr[k * 32 + lane], acc);
    acc = (acc > 0.f) ? acc : expm1f(acc);
    smid[w * 32 + lane] = acc;
    __syncwarp();
    float f0 = bf1[lane], f1 = bf1[lane + 32];
    #pragma unroll
    for (int k = 0; k < 32; k++) {
        float m = smid[w * 32 + k];
        f0 = fmaf(m, Wf1[k * 64 + lane],      f0);
        f1 = fmaf(m, Wf1[k * 64 + lane + 32], f1);
    }
    f0 = (f0 > 0.f) ? f0 : expm1f(f0);
    f1 = (f1 > 0.f) ? f1 : expm1f(f1);
    float part = f0 * Wf2[lane] + f1 * Wf2[lane + 32];
    #pragma unroll
    for (int off = 16; off; off >>= 1) part += __shfl_xor_sync(0xffffffff, part, off);
    if (lane == 0 && node < Nn) out[node] = part + bf2[0];
}

// ---------------- launch ----------------
extern "C" void kernel_launch(void* const* d_in, const int* in_sizes, int n_in,
                              void* d_out, int out_size) {
    const float* x   = (const float*)d_in[0];
    const int*   ei  = (const int*)  d_in[1];
    const float* W1  = (const float*)d_in[3];
    const float* as1 = (const float*)d_in[4];
    const float* ad1 = (const float*)d_in[5];
    const float* b1  = (const float*)d_in[6];
    const float* W2  = (const float*)d_in[7];
    const float* as2 = (const float*)d_in[8];
    const float* ad2 = (const float*)d_in[9];
    const float* b2  = (const float*)d_in[10];
    const float* W3  = (const float*)d_in[11];
    const float* as3 = (const float*)d_in[12];
    const float* ad3 = (const float*)d_in[13];
    const float* b3  = (const float*)d_in[14];
    const float* W4  = (const float*)d_in[15];
    const float* as4 = (const float*)d_in[16];
    const float* ad4 = (const float*)d_in[17];
    const float* b4  = (const float*)d_in[18];
    const float* Wr  = (const float*)d_in[19];
    const float* br  = (const float*)d_in[20];
    const float* Wf1 = (const float*)d_in[21];
    const float* bf1 = (const float*)d_in[22];
    const float* Wf2 = (const float*)d_in[23];
    const float* bf2 = (const float*)d_in[24];
    float* out = (float*)d_out;

    const __half *xhi, *xlo, *ahi, *alo;
    const __half *w1hi, *w1lo, *w2hi, *w2lo, *w3hi, *w3lo, *w4hi, *w4lo;
    { void* p; cudaGetSymbolAddress(&p, g_xhi);  xhi  = (const __half*)p; }
    { void* p; cudaGetSymbolAddress(&p, g_xlo);  xlo  = (const __half*)p; }
    { void* p; cudaGetSymbolAddress(&p, g_ahi);  ahi  = (const __half*)p; }
    { void* p; cudaGetSymbolAddress(&p, g_alo);  alo  = (const __half*)p; }
    { void* p; cudaGetSymbolAddress(&p, g_w1hi); w1hi = (const __half*)p; }
    { void* p; cudaGetSymbolAddress(&p, g_w1lo); w1lo = (const __half*)p; }
    { void* p; cudaGetSymbolAddress(&p, g_w2hi); w2hi = (const __half*)p; }
    { void* p; cudaGetSymbolAddress(&p, g_w2lo); w2lo = (const __half*)p; }
    { void* p; cudaGetSymbolAddress(&p, g_w3hi); w3hi = (const __half*)p; }
    { void* p; cudaGetSymbolAddress(&p, g_w3lo); w3lo = (const __half*)p; }
    { void* p; cudaGetSymbolAddress(&p, g_w4hi); w4hi = (const __half*)p; }
    { void* p; cudaGetSymbolAddress(&p, g_w4lo); w4lo = (const __half*)p; }

    const int NB_SCAN = (Nn + 1023) / 1024;
    const int EB = (Ee + 255) / 256;
    const int AB = (Nn * Hh + 255) / 256;
    const int CONV_N = Nn * 128 + 47104 + Nn;

    conv_k<<<(CONV_N + 255) / 256, 256>>>(x, W1, W2, W3, W4);   // 1 (includes zeroing)
    hist_k<<<EB, 256>>>(ei);                                     // 2
    scan1_k<<<NB_SCAN, 1024>>>();                                // 3
    // 4 — profiled slot: L1 GEMM (128 -> 32). WM=4,WNW=2,MT=1,NF=1 -> 64 rows, 8 warps
    hgemm_k<128, 32, 4, 2, 1, 1, 32><<<(Nn + 63) / 64, 256>>>(xhi, xlo, w1hi, w1lo);
    scan2_k<<<1, 64>>>();
    scan3_k<<<NB_SCAN, 1024>>>();
    fill_k<<<EB, 256>>>(ei);

    // Layer 1 (gemm done)
    alpha_k<8><<<AB, 256>>>(as1, ad1);
    epv_k<<<EB, 256>>>();
    agg_k<8><<<(Nn * 8 + 255) / 256, 256>>>(b1);

    // Layer 2: 32 -> 64. WM=4,WNW=2,MT=1,NF=2 (256 thr, 64 rows/block)
    hgemm_k<32, 64, 4, 2, 1, 2, 32><<<(Nn + 63) / 64, 256>>>(ahi, alo, w2hi, w2lo);
    alpha_k<16><<<AB, 256>>>(as2, ad2);
    epv_k<<<EB, 256>>>();
    agg_k<16><<<(Nn * 16 + 255) / 256, 256>>>(b2);

    // Layer 3: 64 -> 128. WM=4,WNW=2,MT=1,NF=4 (256 thr, 64 rows/block)
    hgemm_k<64, 128, 4, 2, 1, 4, 32><<<(Nn + 63) / 64, 256>>>(ahi, alo, w3hi, w3lo);
    alpha_k<32><<<AB, 256>>>(as3, ad3);
    epv_k<<<EB, 256>>>();
    agg_k<32><<<(Nn * 32 + 255) / 256, 256>>>(b3);

    // Layer 4: 128 -> 256. WM=2,WNW=4,MT=2,NF=4 (256 thr, 64 rows/block)
    hgemm_k<128, 256, 2, 4, 2, 4, 32><<<(Nn + 63) / 64, 256>>>(ahi, alo, w4hi, w4lo);
    alpha_k<64><<<AB, 256>>>(as4, ad4);
    epv_k<<<EB, 256>>>();
    agg_k<64><<<(Nn * 64 + 255) / 256, 256>>>(b4);

    // MLP head
    mlp_k<<<(Nn + 7) / 8, 256>>>(Wr, br, Wf1, bf1, Wf2, bf2, out);
}

// round 16
// speedup vs baseline: 1.2483x; 1.0321x over previous
#include <cuda_runtime.h>
#include <cuda_fp16.h>
#include <mma.h>

using namespace nvcuda;

#define Nn 50000
#define Ee 800000
#define Hh 4

// ---------------- persistent scratch (no allocations allowed) ----------------
__device__ float   g_h[Nn * 256];    // pre-aggregation features fp32
__device__ float   g_act[Nn * 256];  // post-aggregation activations fp32
__device__ __align__(128) __half g_ahi[Nn * 256];  // activations split-hi
__device__ __align__(128) __half g_alo[Nn * 256];  // activations split-lo
__device__ __align__(128) __half g_xhi[Nn * 128];  // input x split-hi
__device__ __align__(128) __half g_xlo[Nn * 128];  // input x split-lo
__device__ __align__(128) __half g_w1hi[4096],  g_w1lo[4096];
__device__ __align__(128) __half g_w2hi[2048],  g_w2lo[2048];
__device__ __align__(128) __half g_w3hi[8192],  g_w3lo[8192];
__device__ __align__(128) __half g_w4hi[32768], g_w4lo[32768];
__device__ float   g_as[Nn * Hh];
__device__ float   g_ad[Nn * Hh];
__device__ float   g_pv[Ee * Hh];
__device__ int     g_counts[Nn];
__device__ int     g_starts[Nn];
__device__ int     g_cursor[Nn];
__device__ int     g_csr[Ee];
__device__ int     g_edst[Ee];
__device__ int     g_bsum[64];

__device__ __forceinline__ void fsplit(float v, __half& hi, __half& lo) {
    hi = __float2half_rn(v);
    lo = __float2half_rn(v - __half2float(hi));
}

// ---------------- fp32 -> split-fp16 conversions + CSR zeroing ----------------
__global__ void conv_k(const float* __restrict__ x,  const float* __restrict__ W1,
                       const float* __restrict__ W2, const float* __restrict__ W3,
                       const float* __restrict__ W4) {
    const int NX = Nn * 128;
    const int NW = 4096 + 2048 + 8192 + 32768;   // 47104
    int i = blockIdx.x * 256 + threadIdx.x;
    if (i < NX) {
        fsplit(x[i], g_xhi[i], g_xlo[i]);
        return;
    }
    int j = i - NX;
    if (j < 4096) {
        fsplit(W1[j], g_w1hi[j], g_w1lo[j]);
        return;
    } else if (j < 4096 + 2048) {
        int p = j - 4096;
        fsplit(W2[p], g_w2hi[p], g_w2lo[p]);
        return;
    } else if (j < 6144 + 8192) {
        int p = j - 6144;
        fsplit(W3[p], g_w3hi[p], g_w3lo[p]);
        return;
    } else if (j < 14336 + 32768) {
        int p = j - 14336;
        fsplit(W4[p], g_w4hi[p], g_w4lo[p]);
        return;
    }
    int k = j - NW;
    if (k < Nn) { g_counts[k] = 0; g_cursor[k] = 0; }
}

// ---------------- CSR build ----------------
__global__ void hist_k(const int* __restrict__ ei) {
    int e = blockIdx.x * blockDim.x + threadIdx.x;
    if (e < Ee) atomicAdd(&g_counts[ei[Ee + e]], 1);
}

__global__ void scan1_k() {
    __shared__ int sh[1024];
    int t = threadIdx.x;
    int i = blockIdx.x * 1024 + t;
    int v = (i < Nn) ? g_counts[i] : 0;
    sh[t] = v;
    __syncthreads();
    #pragma unroll
    for (int off = 1; off < 1024; off <<= 1) {
        int x = (t >= off) ? sh[t - off] : 0;
        __syncthreads();
        sh[t] += x;
        __syncthreads();
    }
    if (i < Nn) g_starts[i] = sh[t];
    if (t == 1023) g_bsum[blockIdx.x] = sh[1023];
}

__global__ void scan2_k() {
    __shared__ int sh[64];
    int t = threadIdx.x;
    const int NB = (Nn + 1023) / 1024;     // 49
    if (t < NB) sh[t] = g_bsum[t];
    __syncthreads();
    if (t == 0) {
        int s = 0;
        for (int i = 0; i < NB; i++) { s += sh[i]; sh[i] = s; }
    }
    __syncthreads();
    if (t < NB) g_bsum[t] = sh[t];
}

__global__ void scan3_k() {
    int i = blockIdx.x * 1024 + threadIdx.x;
    if (i >= Nn) return;
    int off = (blockIdx.x > 0) ? g_bsum[blockIdx.x - 1] : 0;
    g_starts[i] = g_starts[i] - g_counts[i] + off;
}

__global__ void fill_k(const int* __restrict__ ei) {
    int e = blockIdx.x * blockDim.x + threadIdx.x;
    if (e >= Ee) return;
    int src = ei[e];
    int dst = ei[Ee + e];
    int pos = g_starts[dst] + atomicAdd(&g_cursor[dst], 1);
    g_csr[pos]  = src;
    g_edst[pos] = dst;
}

// ---------------- smem-staged split-fp16 tensor-core GEMM ----------------
// h = (Ahi+Alo) @ (Whi+Wlo), lo*lo dropped, fp32 accumulate. Writes fp32 g_h.
template <int IN_, int OUT_, int WM, int WNW, int MT, int NF, int KC>
__global__ void __launch_bounds__(WM * WNW * 32) hgemm_k(const __half* __restrict__ Ahi,
                                                         const __half* __restrict__ Alo,
                                                         const __half* __restrict__ Whi,
                                                         const __half* __restrict__ Wlo) {
    constexpr int NT  = WM * WNW * 32;
    constexpr int MB  = WM * MT * 16;       // block rows
    constexpr int LDA = KC + 8;             // padded (bank-rotating) strides
    constexpr int LDW = OUT_ + 8;
    static_assert(WNW * NF * 16 == OUT_, "col tiling must cover OUT");

    __shared__ __align__(16) __half sAh[MB * LDA];
    __shared__ __align__(16) __half sAl[MB * LDA];
    __shared__ __align__(16) __half sWh[KC * LDW];
    __shared__ __align__(16) __half sWl[KC * LDW];

    int w   = threadIdx.x / 32;
    int wm  = w / WNW;
    int wn  = w % WNW;
    int m0  = blockIdx.x * MB + wm * MT * 16;
    int nc0 = wn * NF * 16;

    wmma::fragment<wmma::accumulator, 16, 16, 16, float> acc[MT][NF];
    #pragma unroll
    for (int mi = 0; mi < MT; mi++)
        #pragma unroll
        for (int ni = 0; ni < NF; ni++) wmma::fill_fragment(acc[mi][ni], 0.0f);

    for (int kc0 = 0; kc0 < IN_; kc0 += KC) {
        for (int idx = threadIdx.x; idx < MB * (KC / 4); idx += NT) {
            int r  = idx / (KC / 4);
            int c4 = (idx % (KC / 4)) * 4;
            int row = blockIdx.x * MB + r;
            uint2 vh = make_uint2(0u, 0u), vl = make_uint2(0u, 0u);
            if (row < Nn) {
                vh = *reinterpret_cast<const uint2*>(&Ahi[row * IN_ + kc0 + c4]);
                vl = *reinterpret_cast<const uint2*>(&Alo[row * IN_ + kc0 + c4]);
            }
            *reinterpret_cast<uint2*>(&sAh[r * LDA + c4]) = vh;
            *reinterpret_cast<uint2*>(&sAl[r * LDA + c4]) = vl;
        }
        for (int idx = threadIdx.x; idx < KC * (OUT_ / 4); idx += NT) {
            int r  = idx / (OUT_ / 4);
            int c4 = (idx % (OUT_ / 4)) * 4;
            *reinterpret_cast<uint2*>(&sWh[r * LDW + c4]) =
                *reinterpret_cast<const uint2*>(&Whi[(kc0 + r) * OUT_ + c4]);
            *reinterpret_cast<uint2*>(&sWl[r * LDW + c4]) =
                *reinterpret_cast<const uint2*>(&Wlo[(kc0 + r) * OUT_ + c4]);
        }
        __syncthreads();

        #pragma unroll
        for (int kt = 0; kt < KC / 16; kt++) {
            wmma::fragment<wmma::matrix_a, 16, 16, 16, __half, wmma::row_major> afh[MT], afl[MT];
            #pragma unroll
            for (int mi = 0; mi < MT; mi++) {
                const __half* ap = &sAh[(wm * MT * 16 + mi * 16) * LDA + kt * 16];
                const __half* lp = &sAl[(wm * MT * 16 + mi * 16) * LDA + kt * 16];
                wmma::load_matrix_sync(afh[mi], ap, LDA);
                wmma::load_matrix_sync(afl[mi], lp, LDA);
            }
            #pragma unroll
            for (int ni = 0; ni < NF; ni++) {
                wmma::fragment<wmma::matrix_b, 16, 16, 16, __half, wmma::row_major> bfh, bfl;
                wmma::load_matrix_sync(bfh, &sWh[kt * 16 * LDW + nc0 + ni * 16], LDW);
                wmma::load_matrix_sync(bfl, &sWl[kt * 16 * LDW + nc0 + ni * 16], LDW);
                #pragma unroll
                for (int mi = 0; mi < MT; mi++) {
                    wmma::mma_sync(acc[mi][ni], afh[mi], bfh, acc[mi][ni]);
                    wmma::mma_sync(acc[mi][ni], afl[mi], bfh, acc[mi][ni]);
                    wmma::mma_sync(acc[mi][ni], afh[mi], bfl, acc[mi][ni]);
                }
            }
        }
        __syncthreads();
    }

    #pragma unroll
    for (int mi = 0; mi < MT; mi++) {
        int row = m0 + mi * 16;
        if (row >= Nn) break;
        #pragma unroll
        for (int ni = 0; ni < NF; ni++)
            wmma::store_matrix_sync(&g_h[row * OUT_ + nc0 + ni * 16], acc[mi][ni],
                                    OUT_, wmma::mem_row_major);
    }
}

// ---------------- per-node attention logits ----------------
template <int C>
__global__ void alpha_k(const float* __restrict__ a_src, const float* __restrict__ a_dst) {
    int i = blockIdx.x * blockDim.x + threadIdx.x;
    if (i >= Nn * Hh) return;
    int node = i >> 2, head = i & 3;
    constexpr int HC = Hh * C;
    const float4* hp = reinterpret_cast<const float4*>(&g_h[node * HC + head * C]);
    const float4* sp = reinterpret_cast<const float4*>(&a_src[head * C]);
    const float4* dp = reinterpret_cast<const float4*>(&a_dst[head * C]);
    float ss = 0.f, sd = 0.f;
    #pragma unroll
    for (int c = 0; c < C / 4; c++) {
        float4 v = hp[c];
        float4 s = __ldg(&sp[c]);
        float4 d = __ldg(&dp[c]);
        ss = fmaf(v.x, s.x, fmaf(v.y, s.y, fmaf(v.z, s.z, fmaf(v.w, s.w, ss))));
        sd = fmaf(v.x, d.x, fmaf(v.y, d.y, fmaf(v.z, d.z, fmaf(v.w, d.w, sd))));
    }
    g_as[i] = ss;
    g_ad[i] = sd;
}

// ---------------- per-edge softmax numerators (all 4 heads) ----------------
__global__ void epv_k() {
    int p = blockIdx.x * blockDim.x + threadIdx.x;
    if (p >= Ee) return;
    int src = g_csr[p];
    int dst = g_edst[p];
    float4 s = *reinterpret_cast<const float4*>(&g_as[src * Hh]);
    float4 d = *reinterpret_cast<const float4*>(&g_ad[dst * Hh]);
    float4 e = make_float4(s.x + d.x, s.y + d.y, s.z + d.z, s.w + d.w);
    e.x = (e.x < 0.f) ? 0.2f * e.x : e.x;
    e.y = (e.y < 0.f) ? 0.2f * e.y : e.y;
    e.z = (e.z < 0.f) ? 0.2f * e.z : e.z;
    e.w = (e.w < 0.f) ? 0.2f * e.w : e.w;
    *reinterpret_cast<float4*>(&g_pv[p * Hh]) =
        make_float4(__expf(e.x), __expf(e.y), __expf(e.z), __expf(e.w));
}

// ---------------- per-dst aggregation: fp32 gather, 8 channels / thread ----------------
template <int C>
__global__ void __launch_bounds__(256) agg_k(const float* __restrict__ bias) {
    constexpr int HC  = Hh * C;
    constexpr int TPN = HC / 8;            // threads per node (8 channels each)
    constexpr int NPB = 256 / TPN;
    int t    = threadIdx.x % TPN;
    int node = blockIdx.x * NPB + threadIdx.x / TPN;
    if (node >= Nn) return;
    int g8   = t * 8;
    int head = g8 / C;

    // implicit self-loop (fp32)
    float es = g_as[node * Hh + head] + g_ad[node * Hh + head];
    es = (es < 0.f) ? 0.2f * es : es;
    float pl = __expf(es);
    float denom = pl;
    float4 hv0 = *reinterpret_cast<const float4*>(&g_h[node * HC + g8]);
    float4 hv1 = *reinterpret_cast<const float4*>(&g_h[node * HC + g8 + 4]);
    float4 a0 = make_float4(pl * hv0.x, pl * hv0.y, pl * hv0.z, pl * hv0.w);
    float4 a1 = make_float4(pl * hv1.x, pl * hv1.y, pl * hv1.z, pl * hv1.w);

    int start = g_starts[node];
    int cnt   = g_counts[node];
    #pragma unroll 4
    for (int j = 0; j < cnt; j++) {
        int   src = __ldg(&g_csr[start + j]);
        float pv  = __ldg(&g_pv[(start + j) * Hh + head]);
        const float4* hp = reinterpret_cast<const float4*>(&g_h[src * HC + g8]);
        float4 h0 = __ldg(&hp[0]);
        float4 h1 = __ldg(&hp[1]);
        denom += pv;
        a0.x = fmaf(pv, h0.x, a0.x);
        a0.y = fmaf(pv, h0.y, a0.y);
        a0.z = fmaf(pv, h0.z, a0.z);
        a0.w = fmaf(pv, h0.w, a0.w);
        a1.x = fmaf(pv, h1.x, a1.x);
        a1.y = fmaf(pv, h1.y, a1.y);
        a1.z = fmaf(pv, h1.z, a1.z);
        a1.w = fmaf(pv, h1.w, a1.w);
    }
    float inv = 1.0f / denom;
    float4 b0 = *reinterpret_cast<const float4*>(&bias[g8]);
    float4 b1 = *reinterpret_cast<const float4*>(&bias[g8 + 4]);
    float o[8];
    o[0] = a0.x * inv + b0.x; o[1] = a0.y * inv + b0.y;
    o[2] = a0.z * inv + b0.z; o[3] = a0.w * inv + b0.w;
    o[4] = a1.x * inv + b1.x; o[5] = a1.y * inv + b1.y;
    o[6] = a1.z * inv + b1.z; o[7] = a1.w * inv + b1.w;
    #pragma unroll
    for (int c = 0; c < 8; c++) o[c] = (o[c] > 0.f) ? o[c] : expm1f(o[c]);

    *reinterpret_cast<float4*>(&g_act[node * HC + g8]) =
        make_float4(o[0], o[1], o[2], o[3]);
    *reinterpret_cast<float4*>(&g_act[node * HC + g8 + 4]) =
        make_float4(o[4], o[5], o[6], o[7]);

    // split-fp16 copy for the next layer's tensor-core GEMM
    __half hi[8], lo[8];
    #pragma unroll
    for (int c = 0; c < 8; c++) fsplit(o[c], hi[c], lo[c]);
    __half2 h01 = __halves2half2(hi[0], hi[1]), h23 = __halves2half2(hi[2], hi[3]);
    __half2 h45 = __halves2half2(hi[4], hi[5]), h67 = __halves2half2(hi[6], hi[7]);
    __half2 l01 = __halves2half2(lo[0], lo[1]), l23 = __halves2half2(lo[2], lo[3]);
    __half2 l45 = __halves2half2(lo[4], lo[5]), l67 = __halves2half2(lo[6], lo[7]);
    uint4 uh, ul;
    uh.x = *reinterpret_cast<unsigned*>(&h01); uh.y = *reinterpret_cast<unsigned*>(&h23);
    uh.z = *reinterpret_cast<unsigned*>(&h45); uh.w = *reinterpret_cast<unsigned*>(&h67);
    ul.x = *reinterpret_cast<unsigned*>(&l01); ul.y = *reinterpret_cast<unsigned*>(&l23);
    ul.z = *reinterpret_cast<unsigned*>(&l45); ul.w = *reinterpret_cast<unsigned*>(&l67);
    *reinterpret_cast<uint4*>(&g_ahi[node * HC + g8]) = uh;
    *reinterpret_cast<uint4*>(&g_alo[node * HC + g8]) = ul;
}

// ---------------- fused MLP head: 256 -> 32 -> 64 -> 1 ----------------
__global__ void __launch_bounds__(256) mlp_k(const float* __restrict__ Wr,  const float* __restrict__ br,
                                             const float* __restrict__ Wf1, const float* __restrict__ bf1,
                                             const float* __restrict__ Wf2, const float* __restrict__ bf2,
                                             float* __restrict__ out) {
    __shared__ float sin_[8 * 256];
    __shared__ float smid[8 * 32];
    int w = threadIdx.x / 32, lane = threadIdx.x % 32;
    int nodeBase = blockIdx.x * 8;

    for (int idx = threadIdx.x; idx < 8 * 256; idx += 256) {
        int node = nodeBase + idx / 256;
        sin_[idx] = (node < Nn) ? g_act[node * 256 + (idx % 256)] : 0.f;
    }
    __syncthreads();

    int node = nodeBase + w;
    float acc = br[lane];
    #pragma unroll 4
    for (int k = 0; k < 256; k++) acc = fmaf(sin_[w * 256 + k], Wr[k * 32 + lane], acc);
    acc = (acc > 0.f) ? acc : expm1f(acc);
    smid[w * 32 + lane] = acc;
    __syncwarp();
    float f0 = bf1[lane], f1 = bf1[lane + 32];
    #pragma unroll
    for (int k = 0; k < 32; k++) {
        float m = smid[w * 32 + k];
        f0 = fmaf(m, Wf1[k * 64 + lane],      f0);
        f1 = fmaf(m, Wf1[k * 64 + lane + 32], f1);
    }
    f0 = (f0 > 0.f) ? f0 : expm1f(f0);
    f1 = (f1 > 0.f) ? f1 : expm1f(f1);
    float part = f0 * Wf2[lane] + f1 * Wf2[lane + 32];
    #pragma unroll
    for (int off = 16; off; off >>= 1) part += __shfl_xor_sync(0xffffffff, part, off);
    if (lane == 0 && node < Nn) out[node] = part + bf2[0];
}

// ---------------- launch ----------------
extern "C" void kernel_launch(void* const* d_in, const int* in_sizes, int n_in,
                              void* d_out, int out_size) {
    const float* x   = (const float*)d_in[0];
    const int*   ei  = (const int*)  d_in[1];
    const float* W1  = (const float*)d_in[3];
    const float* as1 = (const float*)d_in[4];
    const float* ad1 = (const float*)d_in[5];
    const float* b1  = (const float*)d_in[6];
    const float* W2  = (const float*)d_in[7];
    const float* as2 = (const float*)d_in[8];
    const float* ad2 = (const float*)d_in[9];
    const float* b2  = (const float*)d_in[10];
    const float* W3  = (const float*)d_in[11];
    const float* as3 = (const float*)d_in[12];
    const float* ad3 = (const float*)d_in[13];
    const float* b3  = (const float*)d_in[14];
    const float* W4  = (const float*)d_in[15];
    const float* as4 = (const float*)d_in[16];
    const float* ad4 = (const float*)d_in[17];
    const float* b4  = (const float*)d_in[18];
    const float* Wr  = (const float*)d_in[19];
    const float* br  = (const float*)d_in[20];
    const float* Wf1 = (const float*)d_in[21];
    const float* bf1 = (const float*)d_in[22];
    const float* Wf2 = (const float*)d_in[23];
    const float* bf2 = (const float*)d_in[24];
    float* out = (float*)d_out;

    const __half *xhi, *xlo, *ahi, *alo;
    const __half *w1hi, *w1lo, *w2hi, *w2lo, *w3hi, *w3lo, *w4hi, *w4lo;
    { void* p; cudaGetSymbolAddress(&p, g_xhi);  xhi  = (const __half*)p; }
    { void* p; cudaGetSymbolAddress(&p, g_xlo);  xlo  = (const __half*)p; }
    { void* p; cudaGetSymbolAddress(&p, g_ahi);  ahi  = (const __half*)p; }
    { void* p; cudaGetSymbolAddress(&p, g_alo);  alo  = (const __half*)p; }
    { void* p; cudaGetSymbolAddress(&p, g_w1hi); w1hi = (const __half*)p; }
    { void* p; cudaGetSymbolAddress(&p, g_w1lo); w1lo = (const __half*)p; }
    { void* p; cudaGetSymbolAddress(&p, g_w2hi); w2hi = (const __half*)p; }
    { void* p; cudaGetSymbolAddress(&p, g_w2lo); w2lo = (const __half*)p; }
    { void* p; cudaGetSymbolAddress(&p, g_w3hi); w3hi = (const __half*)p; }
    { void* p; cudaGetSymbolAddress(&p, g_w3lo); w3lo = (const __half*)p; }
    { void* p; cudaGetSymbolAddress(&p, g_w4hi); w4hi = (const __half*)p; }
    { void* p; cudaGetSymbolAddress(&p, g_w4lo); w4lo = (const __half*)p; }

    const int NB_SCAN = (Nn + 1023) / 1024;
    const int EB = (Ee + 255) / 256;
    const int AB = (Nn * Hh + 255) / 256;
    const int CONV_N = Nn * 128 + 47104 + Nn;

    conv_k<<<(CONV_N + 255) / 256, 256>>>(x, W1, W2, W3, W4);   // 1 (includes zeroing)
    hist_k<<<EB, 256>>>(ei);                                     // 2
    scan1_k<<<NB_SCAN, 1024>>>();                                // 3
    // 4 — profiled slot: L1 GEMM (128 -> 32)
    hgemm_k<128, 32, 4, 2, 1, 1, 32><<<(Nn + 63) / 64, 256>>>(xhi, xlo, w1hi, w1lo);
    scan2_k<<<1, 64>>>();
    scan3_k<<<NB_SCAN, 1024>>>();
    fill_k<<<EB, 256>>>(ei);

    // Layer 1 (gemm done). HC=32 -> TPN=4
    alpha_k<8><<<AB, 256>>>(as1, ad1);
    epv_k<<<EB, 256>>>();
    agg_k<8><<<(Nn * 4 + 255) / 256, 256>>>(b1);

    // Layer 2: 32 -> 64. HC=64 -> TPN=8
    hgemm_k<32, 64, 4, 2, 1, 2, 32><<<(Nn + 63) / 64, 256>>>(ahi, alo, w2hi, w2lo);
    alpha_k<16><<<AB, 256>>>(as2, ad2);
    epv_k<<<EB, 256>>>();
    agg_k<16><<<(Nn * 8 + 255) / 256, 256>>>(b2);

    // Layer 3: 64 -> 128. HC=128 -> TPN=16
    hgemm_k<64, 128, 4, 2, 1, 4, 32><<<(Nn + 63) / 64, 256>>>(ahi, alo, w3hi, w3lo);
    alpha_k<32><<<AB, 256>>>(as3, ad3);
    epv_k<<<EB, 256>>>();
    agg_k<32><<<(Nn * 16 + 255) / 256, 256>>>(b3);

    // Layer 4: 128 -> 256. HC=256 -> TPN=32
    hgemm_k<128, 256, 2, 4, 2, 4, 32><<<(Nn + 63) / 64, 256>>>(ahi, alo, w4hi, w4lo);
    alpha_k<64><<<AB, 256>>>(as4, ad4);
    epv_k<<<EB, 256>>>();
    agg_k<64><<<(Nn * 32 + 255) / 256, 256>>>(b4);

    // MLP head
    mlp_k<<<(Nn + 7) / 8, 256>>>(Wr, br, Wf1, bf1, Wf2, bf2, out);
}